// round 15
// baseline (speedup 1.0000x reference)
#include <cuda_runtime.h>
#include <cuda_fp16.h>
#include <math.h>
#include <stdint.h>

#define SS   17
#define NPOS 4096
#define DD   256
#define NH   8
#define MTOT (SS * NPOS)   // 69632

// ---------------- scratch (allocation-free: device globals) ----------------
// s-major layout (row = s*NPOS + n), all fp16
__device__ __half g_h16[(size_t)MTOT * DD];
__device__ __half g_q16[(size_t)MTOT * DD];
__device__ __half g_k16[(size_t)MTOT * DD];
__device__ __half g_v16[(size_t)MTOT * DD];
__device__ __half g_o16[(size_t)MTOT * DD];
__device__ __half g_w16[4][DD * DD];          // fp16(Wq,Wk,Wv,Wo)
__device__ unsigned char g_mask[SS * NPOS];   // rows 1..16 = msta (row 0 unused)

// ---------------- helpers ----------------
__device__ __forceinline__ uint32_t smem_u32(const void* p) {
    uint32_t a;
    asm("{ .reg .u64 t; cvta.to.shared.u64 t, %1; cvt.u32.u64 %0, t; }" : "=r"(a) : "l"(p));
    return a;
}
__device__ __forceinline__ void cpa16(uint32_t dst, const void* src) {
    asm volatile("cp.async.cg.shared.global [%0], [%1], 16;" :: "r"(dst), "l"(src));
}
#define CP_COMMIT() asm volatile("cp.async.commit_group;" ::: "memory")
#define CP_WAIT(n)  asm volatile("cp.async.wait_group %0;" :: "n"(n) : "memory")

__device__ __forceinline__ void ldsm4(uint32_t* r, uint32_t addr) {
    asm volatile("ldmatrix.sync.aligned.m8n8.x4.shared.b16 {%0,%1,%2,%3}, [%4];"
                 : "=r"(r[0]), "=r"(r[1]), "=r"(r[2]), "=r"(r[3]) : "r"(addr));
}
// fp16 mma: D(4xf32) += A(4xb32) * B(2xb32)
__device__ __forceinline__ void mma16(float* c, const uint32_t* a, uint32_t b0, uint32_t b1) {
    asm volatile(
        "mma.sync.aligned.m16n8k16.row.col.f32.f16.f16.f32 "
        "{%0,%1,%2,%3}, {%4,%5,%6,%7}, {%8,%9}, {%0,%1,%2,%3};"
        : "+f"(c[0]), "+f"(c[1]), "+f"(c[2]), "+f"(c[3])
        : "r"(a[0]), "r"(a[1]), "r"(a[2]), "r"(a[3]), "r"(b0), "r"(b1));
}

// ---------------- mask canonicalization (dtype-robust, parallel) ----------------
__global__ void mask_prep(const unsigned char* __restrict__ mraw) {
    __shared__ int s_nz1;
    int tid = threadIdx.x;
    if (tid == 0) s_nz1 = 0;
    __syncthreads();
    int l1 = 0;
    for (int i = tid; i < 4096; i += blockDim.x)
        if ((i & 3) == 1 && mraw[i] != 0) l1 = 1;
    if (l1) atomicOr(&s_nz1, 1);
    __syncthreads();
    bool u8fmt = (s_nz1 != 0);
    const unsigned int* mw = (const unsigned int*)mraw;
    int i = blockIdx.x * 1024 + tid;
    for (int r = 0; r < 4; r++, i += 256) {
        unsigned char m = u8fmt ? (mraw[i] != 0) : (mw[i] != 0u);
        g_mask[NPOS + i] = m;
    }
}

// ---------------- fp16 pre-conversion (rna) ----------------
__global__ void conv_h16(const float4* __restrict__ src) {
    size_t i = (size_t)blockIdx.x * 256 + threadIdx.x;   // 8 floats per thread
    float4 a = src[2 * i];
    float4 b = src[2 * i + 1];
    __half2 h[4];
    h[0] = __floats2half2_rn(a.x, a.y);
    h[1] = __floats2half2_rn(a.z, a.w);
    h[2] = __floats2half2_rn(b.x, b.y);
    h[3] = __floats2half2_rn(b.z, b.w);
    *(uint4*)(g_h16 + i * 8) = *(uint4*)h;
}
__global__ void conv_w16(const float4* __restrict__ w0, const float4* __restrict__ w1,
                         const float4* __restrict__ w2, const float4* __restrict__ w3) {
    const float4* srcs[4] = {w0, w1, w2, w3};
    int mat = blockIdx.x >> 5;
    int i = (blockIdx.x & 31) * 256 + threadIdx.x;
    float4 a = srcs[mat][2 * i];
    float4 b = srcs[mat][2 * i + 1];
    __half2 h[4];
    h[0] = __floats2half2_rn(a.x, a.y);
    h[1] = __floats2half2_rn(a.z, a.w);
    h[2] = __floats2half2_rn(b.x, b.y);
    h[3] = __floats2half2_rn(b.z, b.w);
    *(uint4*)(&g_w16[mat][0] + (size_t)i * 8) = *(uint4*)h;
}

// ===== fused QKV GEMM (fp16), A-PERSISTENT: grid 544, 24-iter pipeline =====
// smem: A[4 chunks][16KB] = 64KB persistent + W ring 3x16KB = 112KB total.
#define QKV_SMEM (7 * 16384)                 // 114688 B

__global__ void __launch_bounds__(256, 2)
gemm_qkv(const __half* __restrict__ A,
         const __half* __restrict__ W0, const __half* __restrict__ W1,
         const __half* __restrict__ W2,
         __half* __restrict__ C0, __half* __restrict__ C1, __half* __restrict__ C2) {
    extern __shared__ char smc[];
    const uint32_t sb = smem_u32(smc);
    const int bm = blockIdx.x * 128;
    const __half* Ws[3] = {W0, W1, W2};
    __half* Cs[3] = {C0, C1, C2};

    const int tid = threadIdx.x;
    const int lane = tid & 31;
    const int wid = tid >> 5;
    const int warpM = wid >> 1;
    const int warpN = wid & 1;
    const int g = lane >> 2;
    const int t = lane & 3;
    const int rr = lane & 7;
    const int half8 = (lane >> 3) & 1;
    const int hi = lane >> 4;
    const uint32_t rowA0 = (uint32_t)(warpM * 32 + half8 * 8 + rr);
    const uint32_t rowB0 = (uint32_t)(warpN * 64 + half8 * 8 + rr);

    const int lrow = tid >> 3;        // 0..31
    const int lcj  = tid & 7;         // chunk 0..7

    // ---- load full A tile once: 4 k-chunks of [128 x 64] fp16 ----
    #pragma unroll
    for (int c = 0; c < 4; c++)
        #pragma unroll
        for (int i = 0; i < 4; i++) {
            int row = lrow + i * 32;
            uint32_t sw = (uint32_t)(lcj ^ (row & 7));
            cpa16(sb + (uint32_t)(c * 16384 + row * 128) + sw * 16,
                  A + (size_t)(bm + row) * DD + c * 64 + lcj * 8);
        }
    CP_COMMIT();

    // W prefetch for global iteration j: oc=j>>2 (out,bn), kk=j&3
    auto loadW = [&](int j) {
        int oc = j >> 2;
        int kk = j & 3;
        const __half* W = Ws[oc >> 1];
        int bn = (oc & 1) * 128;
        uint32_t base = (uint32_t)(65536 + (j % 3) * 16384);
        #pragma unroll
        for (int i = 0; i < 4; i++) {
            int row = lrow + i * 32;
            uint32_t sw = (uint32_t)(lcj ^ (row & 7));
            cpa16(sb + base + (uint32_t)(row * 128) + sw * 16,
                  W + (size_t)(bn + row) * DD + kk * 64 + lcj * 8);
        }
    };

    loadW(0); CP_COMMIT();
    loadW(1); CP_COMMIT();

    float acc[2][8][4];

    #pragma unroll 1
    for (int j = 0; j < 24; j++) {
        if ((j & 3) == 0) {
            #pragma unroll
            for (int m = 0; m < 2; m++)
                #pragma unroll
                for (int n = 0; n < 8; n++)
                    #pragma unroll
                    for (int q = 0; q < 4; q++) acc[m][n][q] = 0.f;
        }
        if (j < 23) CP_WAIT(1); else CP_WAIT(0);
        __syncthreads();
        if (j < 22) { loadW(j + 2); CP_COMMIT(); }

        const uint32_t aBase = sb + (uint32_t)((j & 3) * 16384) + rowA0 * 128;
        const uint32_t bBase = sb + (uint32_t)(65536 + (j % 3) * 16384) + rowB0 * 128;
        #pragma unroll
        for (int ks = 0; ks < 4; ks++) {
            const uint32_t cob = (uint32_t)(((2 * ks + hi) ^ rr) << 4);
            uint32_t a0[4], a1[4];
            ldsm4(a0, aBase + cob);
            ldsm4(a1, aBase + 16 * 128 + cob);
            uint32_t bt[4][4];
            #pragma unroll
            for (int jj = 0; jj < 4; jj++)
                ldsm4(bt[jj], bBase + (uint32_t)(jj * 16 * 128) + cob);
            #pragma unroll
            for (int jj = 0; jj < 4; jj++) {
                mma16(acc[0][2 * jj],     a0, bt[jj][0], bt[jj][2]);
                mma16(acc[0][2 * jj + 1], a0, bt[jj][1], bt[jj][3]);
                mma16(acc[1][2 * jj],     a1, bt[jj][0], bt[jj][2]);
                mma16(acc[1][2 * jj + 1], a1, bt[jj][1], bt[jj][3]);
            }
        }

        if ((j & 3) == 3) {     // finished K for this (out, bn): store block
            int oc = j >> 2;
            __half* C = Cs[oc >> 1];
            int bn = (oc & 1) * 128;
            #pragma unroll
            for (int m = 0; m < 2; m++) {
                int r0 = bm + warpM * 32 + m * 16 + g;
                #pragma unroll
                for (int n = 0; n < 8; n++) {
                    int c0 = bn + warpN * 64 + n * 8 + 2 * t;
                    *(__half2*)(C + (size_t)r0 * DD + c0) =
                        __floats2half2_rn(acc[m][n][0], acc[m][n][1]);
                    *(__half2*)(C + (size_t)(r0 + 8) * DD + c0) =
                        __floats2half2_rn(acc[m][n][2], acc[m][n][3]);
                }
            }
        }
    }
}

// ========== fused Wo GEMM (fp16) + residual + bias + LayerNorm =============
#define WO_STAGE_B 49152
#define WO_SMEM    (3 * WO_STAGE_B)          // 147456 B

__global__ void __launch_bounds__(512, 1)
gemm_wo_ln(const __half* __restrict__ A, const __half* __restrict__ W,
           const float* __restrict__ h, const float* __restrict__ bo,
           const float* __restrict__ gg, const float* __restrict__ bb,
           float* __restrict__ outp) {
    extern __shared__ char smc[];
    const uint32_t sb = smem_u32(smc);
    float2* red = (float2*)smc;
    const int tid = threadIdx.x;
    const int lane = tid & 31;
    const int wid = tid >> 5;
    const int warpM = wid >> 2;
    const int warpN = wid & 3;
    const int bm = blockIdx.x * 128;
    const int g = lane >> 2;
    const int t = lane & 3;
    const int rr = lane & 7;
    const int half8 = (lane >> 3) & 1;
    const int hi = lane >> 4;
    const uint32_t rowA0 = (uint32_t)(warpM * 32 + half8 * 8 + rr);
    const uint32_t rowB0 = (uint32_t)(warpN * 64 + half8 * 8 + rr);

    float acc[2][8][4];
    #pragma unroll
    for (int m = 0; m < 2; m++)
        #pragma unroll
        for (int n = 0; n < 8; n++)
            #pragma unroll
            for (int j = 0; j < 4; j++) acc[m][n][j] = 0.f;

    const int lrow = tid >> 3;        // 0..63
    const int lcj  = tid & 7;

    auto load_stage = [&](int buf, int k0) {
        #pragma unroll
        for (int i = 0; i < 2; i++) {    // A: 128 rows
            int row = lrow + i * 64;
            uint32_t sw = (uint32_t)(lcj ^ (row & 7));
            cpa16(sb + (uint32_t)(buf * WO_STAGE_B + row * 128) + sw * 16,
                  A + (size_t)(bm + row) * DD + k0 + lcj * 8);
        }
        #pragma unroll
        for (int i = 0; i < 4; i++) {    // W: 256 rows
            int row = lrow + i * 64;
            uint32_t sw = (uint32_t)(lcj ^ (row & 7));
            cpa16(sb + (uint32_t)(buf * WO_STAGE_B + 16384 + row * 128) + sw * 16,
                  W + (size_t)row * DD + k0 + lcj * 8);
        }
    };

    load_stage(0, 0);  CP_COMMIT();
    load_stage(1, 64); CP_COMMIT();

    #pragma unroll 1
    for (int kk = 0; kk < 4; kk++) {
        if (kk < 3) CP_WAIT(1); else CP_WAIT(0);
        __syncthreads();
        if (kk < 2) { load_stage((kk + 2) % 3, (kk + 2) * 64); CP_COMMIT(); }

        const uint32_t aBase = sb + (uint32_t)((kk % 3) * WO_STAGE_B) + rowA0 * 128;
        const uint32_t bBase = sb + (uint32_t)((kk % 3) * WO_STAGE_B + 16384) + rowB0 * 128;
        #pragma unroll
        for (int ks = 0; ks < 4; ks++) {
            const uint32_t cob = (uint32_t)(((2 * ks + hi) ^ rr) << 4);
            uint32_t a0[4], a1[4];
            ldsm4(a0, aBase + cob);
            ldsm4(a1, aBase + 16 * 128 + cob);
            uint32_t bt[4][4];
            #pragma unroll
            for (int j = 0; j < 4; j++) ldsm4(bt[j], bBase + (uint32_t)(j * 16 * 128) + cob);
            #pragma unroll
            for (int j = 0; j < 4; j++) {
                mma16(acc[0][2 * j],     a0, bt[j][0], bt[j][2]);
                mma16(acc[0][2 * j + 1], a0, bt[j][1], bt[j][3]);
                mma16(acc[1][2 * j],     a1, bt[j][0], bt[j][2]);
                mma16(acc[1][2 * j + 1], a1, bt[j][1], bt[j][3]);
            }
        }
    }
    __syncthreads();   // mma reads done; smem reused for LN reduction

    // ---- epilogue: x = h + y + bo; per-row mean/var; normalize; store ----
    float2 bo2[8];
    #pragma unroll
    for (int n = 0; n < 8; n++)
        bo2[n] = *(const float2*)(bo + warpN * 64 + n * 8 + 2 * t);

    float s1[2][2], s2[2][2];
    #pragma unroll
    for (int m = 0; m < 2; m++) {
        int r0 = bm + warpM * 32 + m * 16 + g;
        s1[m][0] = s1[m][1] = s2[m][0] = s2[m][1] = 0.f;
        #pragma unroll
        for (int n = 0; n < 8; n++) {
            int coln = warpN * 64 + n * 8 + 2 * t;
            float2 ha = *(const float2*)(h + (size_t)r0 * DD + coln);
            float2 hb = *(const float2*)(h + (size_t)(r0 + 8) * DD + coln);
            float x0 = acc[m][n][0] + ha.x + bo2[n].x;
            float x1 = acc[m][n][1] + ha.y + bo2[n].y;
            float x2 = acc[m][n][2] + hb.x + bo2[n].x;
            float x3 = acc[m][n][3] + hb.y + bo2[n].y;
            acc[m][n][0] = x0; acc[m][n][1] = x1;
            acc[m][n][2] = x2; acc[m][n][3] = x3;
            s1[m][0] += x0 + x1;            s1[m][1] += x2 + x3;
            s2[m][0] += x0 * x0 + x1 * x1;  s2[m][1] += x2 * x2 + x3 * x3;
        }
    }
    #pragma unroll
    for (int m = 0; m < 2; m++)
        #pragma unroll
        for (int hh = 0; hh < 2; hh++) {
            s1[m][hh] += __shfl_xor_sync(0xffffffffu, s1[m][hh], 1);
            s1[m][hh] += __shfl_xor_sync(0xffffffffu, s1[m][hh], 2);
            s2[m][hh] += __shfl_xor_sync(0xffffffffu, s2[m][hh], 1);
            s2[m][hh] += __shfl_xor_sync(0xffffffffu, s2[m][hh], 2);
        }
    if (t == 0) {
        #pragma unroll
        for (int m = 0; m < 2; m++)
            #pragma unroll
            for (int hh = 0; hh < 2; hh++) {
                int row = warpM * 32 + m * 16 + g + hh * 8;
                red[row * 4 + warpN] = make_float2(s1[m][hh], s2[m][hh]);
            }
    }
    __syncthreads();

    #pragma unroll
    for (int m = 0; m < 2; m++) {
        #pragma unroll
        for (int hh = 0; hh < 2; hh++) {
            int row = warpM * 32 + m * 16 + g + hh * 8;
            float a1 = 0.f, a2 = 0.f;
            #pragma unroll
            for (int w2 = 0; w2 < 4; w2++) {
                float2 p = red[row * 4 + w2];
                a1 += p.x; a2 += p.y;
            }
            float mu = a1 * (1.0f / DD);
            float var = a2 * (1.0f / DD) - mu * mu;
            float rinv = rsqrtf(var + 1e-5f);
            size_t rbase = (size_t)(bm + row) * DD;
            #pragma unroll
            for (int n = 0; n < 8; n++) {
                int coln = warpN * 64 + n * 8 + 2 * t;
                float2 gv = *(const float2*)(gg + coln);
                float2 bv = *(const float2*)(bb + coln);
                float x0 = acc[m][n][hh * 2 + 0];
                float x1 = acc[m][n][hh * 2 + 1];
                float2 o;
                o.x = (x0 - mu) * rinv * gv.x + bv.x;
                o.y = (x1 - mu) * rinv * gv.y + bv.y;
                *(float2*)(outp + rbase + coln) = o;
            }
        }
    }
}

// ------- per-position attention (fp16 streams, deferred softmax) -----------
__global__ __launch_bounds__(256) void attn_kernel() {
    const int n = blockIdx.x;
    const int w = threadIdx.x >> 5;
    const int lane = threadIdx.x & 31;
    __shared__ float  sq[NH][SS][36];        // fp32 q (converted once)
    __shared__ float  satt[NH][SS][20];      // unnormalized exp(score)
    __shared__ __half st16[NH][2][SS][32];   // fp16 staging: [0]=q, [1]=k

    const size_t rowbase = (size_t)n * DD + w * 32;

    // ---- async stage q,k fp16: 17 rows x 4 chunks x 2 arrays = 136 chunks --
    {
        const __half* srcs[2] = {g_q16 + rowbase, g_k16 + rowbase};
        const uint32_t d0 = smem_u32(&st16[w][0][0][0]);
        #pragma unroll
        for (int pass = 0; pass < 5; pass++) {
            int idx = pass * 32 + lane;
            if (idx < 136) {
                int s = idx >> 3;
                int which = (idx >> 2) & 1;
                int c = idx & 3;
                cpa16(d0 + (uint32_t)((which * SS + s) * 64 + c * 16),
                      srcs[which] + (size_t)s * NPOS * DD + c * 8);
            }
        }
        CP_COMMIT();
    }

    // ---- mask + v loads overlap the cp.async group ----
    unsigned char mr = 0;
    if (lane >= 1 && lane < SS) mr = g_mask[lane * NPOS + n];

    float vv[SS];
    const size_t coloff = rowbase + lane;
    #pragma unroll
    for (int s = 0; s < SS; s++)
        vv[s] = __half2float(g_v16[coloff + (size_t)s * NPOS * DD]);

    unsigned bits = __ballot_sync(0xffffffffu, mr != 0);
    if (bits & 0x1FFFEu) bits |= 1u;

    CP_WAIT(0);
    __syncwarp();

    // convert q -> fp32 smem (272 half2 per warp)
    #pragma unroll
    for (int j = 0; j < 9; j++) {
        int idx = j * 32 + lane;
        if (idx < 272) {
            int s = idx >> 4;
            int c2 = idx & 15;
            float2 f = __half22float2(*(__half2*)&st16[w][0][s][2 * c2]);
            *(float2*)&sq[w][s][2 * c2] = f;
        }
    }
    __syncwarp();

    const float scale = 0.17677669529663687f;  // 1/sqrt(32)
    const bool key_act = (lane < SS) && ((bits >> lane) & 1u);

    // k row -> registers (fp16 -> fp32), loop-invariant across s
    float kk[32];
    if (key_act) {
        #pragma unroll
        for (int j = 0; j < 16; j++) {
            float2 f = __half22float2(*(__half2*)&st16[w][1][lane][2 * j]);
            kk[2 * j] = f.x;
            kk[2 * j + 1] = f.y;
        }
    }

    // score phase: store UNNORMALIZED p
    #pragma unroll 1
    for (int s = 0; s < SS; s++) {
        if (!((bits >> s) & 1u)) continue;      // warp-uniform
        float p = 0.f;
        if (key_act) {
            float a0 = 0.f, a1 = 0.f;
            #pragma unroll
            for (int c = 0; c < 32; c += 8) {
                float4 q0 = *(const float4*)&sq[w][s][c];       // broadcast
                float4 q1 = *(const float4*)&sq[w][s][c + 4];   // broadcast
                a0 += q0.x * kk[c + 0] + q0.y * kk[c + 1] +
                      q0.z * kk[c + 2] + q0.w * kk[c + 3];
                a1 += q1.x * kk[c + 4] + q1.y * kk[c + 5] +
                      q1.z * kk[c + 6] + q1.w * kk[c + 7];
            }
            p = __expf((a0 + a1) * scale);      // shift-invariant: no max needed
        }
        if (lane < SS) satt[w][s][lane] = p;
    }
    __syncwarp();

    // out phase: res = (Σ p·v) / (Σ p)
    #pragma unroll 1
    for (int s = 0; s < SS; s++) {
        float res;
        if ((bits >> s) & 1u) {
            const float4* arow = (const float4*)&satt[w][s][0];
            float acc = 0.f, ps = 0.f;
            #pragma unroll
            for (int j = 0; j < 4; j++) {
                float4 a4 = arow[j];
                acc += a4.x * vv[4 * j + 0] + a4.y * vv[4 * j + 1] +
                       a4.z * vv[4 * j + 2] + a4.w * vv[4 * j + 3];
                ps  += (a4.x + a4.y) + (a4.z + a4.w);
            }
            float a16 = satt[w][s][16];
            acc += a16 * vv[16];
            ps  += a16;
            res = acc * __frcp_rn(ps);
        } else {
            res = vv[s];
        }
        g_o16[coloff + (size_t)s * NPOS * DD] = __float2half_rn(res);
    }
}

// ---------------- launch ----------------
extern "C" void kernel_launch(void* const* d_in, const int* in_sizes, int n_in,
                              void* d_out, int out_size) {
    (void)in_sizes; (void)n_in; (void)out_size;
    const float* h  = (const float*)d_in[0];
    const void*  mm = d_in[2];
    const float* Wq = (const float*)d_in[3];
    const float* Wk = (const float*)d_in[4];
    const float* Wv = (const float*)d_in[5];
    const float* Wo = (const float*)d_in[6];
    const float* bo = (const float*)d_in[7];
    const float* lg = (const float*)d_in[8];
    const float* lb = (const float*)d_in[9];
    float* out = (float*)d_out;

    __half *ph, *pq, *pk, *pv, *po, *pw;
    cudaGetSymbolAddress((void**)&ph, g_h16);
    cudaGetSymbolAddress((void**)&pq, g_q16);
    cudaGetSymbolAddress((void**)&pk, g_k16);
    cudaGetSymbolAddress((void**)&pv, g_v16);
    cudaGetSymbolAddress((void**)&po, g_o16);
    cudaGetSymbolAddress((void**)&pw, g_w16);

    cudaFuncSetAttribute(gemm_qkv, cudaFuncAttributeMaxDynamicSharedMemorySize, QKV_SMEM);
    cudaFuncSetAttribute(gemm_wo_ln, cudaFuncAttributeMaxDynamicSharedMemorySize, WO_SMEM);

    mask_prep<<<64, 256>>>((const unsigned char*)mm);
    conv_h16<<<MTOT * DD / 2048, 256>>>((const float4*)h);
    conv_w16<<<128, 256>>>((const float4*)Wq, (const float4*)Wk,
                           (const float4*)Wv, (const float4*)Wo);

    gemm_qkv<<<MTOT / 128, 256, QKV_SMEM>>>(
        ph, pw + 0 * DD * DD, pw + 1 * DD * DD, pw + 2 * DD * DD, pq, pk, pv);

    attn_kernel<<<NPOS, 256>>>();

    gemm_wo_ln<<<MTOT / 128, 512, WO_SMEM>>>(po, pw + 3 * DD * DD,
                                             h, bo, lg, lb, out);
}

// round 16
// speedup vs baseline: 1.4355x; 1.4355x over previous
#include <cuda_runtime.h>
#include <cuda_fp16.h>
#include <math.h>
#include <stdint.h>

#define SS   17
#define NPOS 4096
#define DD   256
#define NH   8
#define MTOT (SS * NPOS)   // 69632

// ---------------- scratch (allocation-free: device globals) ----------------
// s-major layout (row = s*NPOS + n), all fp16
__device__ __half g_h16[(size_t)MTOT * DD];
__device__ __half g_q16[(size_t)MTOT * DD];
__device__ __half g_k16[(size_t)MTOT * DD];
__device__ __half g_v16[(size_t)MTOT * DD];
__device__ __half g_o16[(size_t)MTOT * DD];
__device__ __half g_w16[4][DD * DD];          // fp16(Wq,Wk,Wv,Wo)
__device__ unsigned char g_mask[SS * NPOS];   // rows 1..16 = msta (row 0 unused)

// ---------------- helpers ----------------
__device__ __forceinline__ uint32_t smem_u32(const void* p) {
    uint32_t a;
    asm("{ .reg .u64 t; cvta.to.shared.u64 t, %1; cvt.u32.u64 %0, t; }" : "=r"(a) : "l"(p));
    return a;
}
__device__ __forceinline__ void cpa16(uint32_t dst, const void* src) {
    asm volatile("cp.async.cg.shared.global [%0], [%1], 16;" :: "r"(dst), "l"(src));
}
#define CP_COMMIT() asm volatile("cp.async.commit_group;" ::: "memory")
#define CP_WAIT(n)  asm volatile("cp.async.wait_group %0;" :: "n"(n) : "memory")

__device__ __forceinline__ void ldsm4(uint32_t* r, uint32_t addr) {
    asm volatile("ldmatrix.sync.aligned.m8n8.x4.shared.b16 {%0,%1,%2,%3}, [%4];"
                 : "=r"(r[0]), "=r"(r[1]), "=r"(r[2]), "=r"(r[3]) : "r"(addr));
}
// fp16 mma: D(4xf32) += A(4xb32) * B(2xb32)
__device__ __forceinline__ void mma16(float* c, const uint32_t* a, uint32_t b0, uint32_t b1) {
    asm volatile(
        "mma.sync.aligned.m16n8k16.row.col.f32.f16.f16.f32 "
        "{%0,%1,%2,%3}, {%4,%5,%6,%7}, {%8,%9}, {%0,%1,%2,%3};"
        : "+f"(c[0]), "+f"(c[1]), "+f"(c[2]), "+f"(c[3])
        : "r"(a[0]), "r"(a[1]), "r"(a[2]), "r"(a[3]), "r"(b0), "r"(b1));
}

// ---------------- mask canonicalization (dtype-robust, parallel) ----------------
__global__ void mask_prep(const unsigned char* __restrict__ mraw) {
    __shared__ int s_nz1;
    int tid = threadIdx.x;
    if (tid == 0) s_nz1 = 0;
    __syncthreads();
    int l1 = 0;
    for (int i = tid; i < 4096; i += blockDim.x)
        if ((i & 3) == 1 && mraw[i] != 0) l1 = 1;
    if (l1) atomicOr(&s_nz1, 1);
    __syncthreads();
    bool u8fmt = (s_nz1 != 0);
    const unsigned int* mw = (const unsigned int*)mraw;
    int i = blockIdx.x * 1024 + tid;
    for (int r = 0; r < 4; r++, i += 256) {
        unsigned char m = u8fmt ? (mraw[i] != 0) : (mw[i] != 0u);
        g_mask[NPOS + i] = m;
    }
}

// ---------------- fp16 pre-conversion (rna) ----------------
__global__ void conv_h16(const float4* __restrict__ src) {
    size_t i = (size_t)blockIdx.x * 256 + threadIdx.x;   // 8 floats per thread
    float4 a = src[2 * i];
    float4 b = src[2 * i + 1];
    __half2 h[4];
    h[0] = __floats2half2_rn(a.x, a.y);
    h[1] = __floats2half2_rn(a.z, a.w);
    h[2] = __floats2half2_rn(b.x, b.y);
    h[3] = __floats2half2_rn(b.z, b.w);
    *(uint4*)(g_h16 + i * 8) = *(uint4*)h;
}
__global__ void conv_w16(const float4* __restrict__ w0, const float4* __restrict__ w1,
                         const float4* __restrict__ w2, const float4* __restrict__ w3) {
    const float4* srcs[4] = {w0, w1, w2, w3};
    int mat = blockIdx.x >> 5;
    int i = (blockIdx.x & 31) * 256 + threadIdx.x;
    float4 a = srcs[mat][2 * i];
    float4 b = srcs[mat][2 * i + 1];
    __half2 h[4];
    h[0] = __floats2half2_rn(a.x, a.y);
    h[1] = __floats2half2_rn(a.z, a.w);
    h[2] = __floats2half2_rn(b.x, b.y);
    h[3] = __floats2half2_rn(b.z, b.w);
    *(uint4*)(&g_w16[mat][0] + (size_t)i * 8) = *(uint4*)h;
}

// ===== fused QKV GEMM (fp16): grid (3, 544), BN=256, 512 threads ===========
// Per CTA: one output matrix, full 256 cols, 128 rows. Stage = A 16KB + W 32KB.
#define QKV_STAGE_B 49152
#define QKV_SMEM    (3 * QKV_STAGE_B)        // 147456 B

__global__ void __launch_bounds__(512, 1)
gemm_qkv(const __half* __restrict__ A,
         const __half* __restrict__ W0, const __half* __restrict__ W1,
         const __half* __restrict__ W2,
         __half* __restrict__ C0, __half* __restrict__ C1, __half* __restrict__ C2) {
    extern __shared__ char smc[];
    const uint32_t sb = smem_u32(smc);
    const int out = blockIdx.x;
    const int bm = blockIdx.y * 128;
    const __half* W = (out == 0) ? W0 : (out == 1) ? W1 : W2;
    __half* C = (out == 0) ? C0 : (out == 1) ? C1 : C2;

    const int tid = threadIdx.x;
    const int lane = tid & 31;
    const int wid = tid >> 5;
    const int warpM = wid >> 2;       // 0..3
    const int warpN = wid & 3;        // 0..3
    const int g = lane >> 2;
    const int t = lane & 3;
    const int rr = lane & 7;
    const int half8 = (lane >> 3) & 1;
    const int hi = lane >> 4;
    const uint32_t rowA0 = (uint32_t)(warpM * 32 + half8 * 8 + rr);
    const uint32_t rowB0 = (uint32_t)(warpN * 64 + half8 * 8 + rr);

    float acc[2][8][4];
    #pragma unroll
    for (int m = 0; m < 2; m++)
        #pragma unroll
        for (int n = 0; n < 8; n++)
            #pragma unroll
            for (int j = 0; j < 4; j++) acc[m][n][j] = 0.f;

    const int lrow = tid >> 3;        // 0..63
    const int lcj  = tid & 7;

    auto load_stage = [&](int buf, int k0) {
        #pragma unroll
        for (int i = 0; i < 2; i++) {    // A: 128 rows
            int row = lrow + i * 64;
            uint32_t sw = (uint32_t)(lcj ^ (row & 7));
            cpa16(sb + (uint32_t)(buf * QKV_STAGE_B + row * 128) + sw * 16,
                  A + (size_t)(bm + row) * DD + k0 + lcj * 8);
        }
        #pragma unroll
        for (int i = 0; i < 4; i++) {    // W: 256 rows
            int row = lrow + i * 64;
            uint32_t sw = (uint32_t)(lcj ^ (row & 7));
            cpa16(sb + (uint32_t)(buf * QKV_STAGE_B + 16384 + row * 128) + sw * 16,
                  W + (size_t)row * DD + k0 + lcj * 8);
        }
    };

    load_stage(0, 0);  CP_COMMIT();
    load_stage(1, 64); CP_COMMIT();

    #pragma unroll 1
    for (int kk = 0; kk < 4; kk++) {
        if (kk < 3) CP_WAIT(1); else CP_WAIT(0);
        __syncthreads();
        if (kk < 2) { load_stage((kk + 2) % 3, (kk + 2) * 64); CP_COMMIT(); }

        const uint32_t aBase = sb + (uint32_t)((kk % 3) * QKV_STAGE_B) + rowA0 * 128;
        const uint32_t bBase = sb + (uint32_t)((kk % 3) * QKV_STAGE_B + 16384) + rowB0 * 128;
        #pragma unroll
        for (int ks = 0; ks < 4; ks++) {
            const uint32_t cob = (uint32_t)(((2 * ks + hi) ^ rr) << 4);
            uint32_t a0[4], a1[4];
            ldsm4(a0, aBase + cob);
            ldsm4(a1, aBase + 16 * 128 + cob);
            uint32_t bt[4][4];
            #pragma unroll
            for (int j = 0; j < 4; j++) ldsm4(bt[j], bBase + (uint32_t)(j * 16 * 128) + cob);
            #pragma unroll
            for (int j = 0; j < 4; j++) {
                mma16(acc[0][2 * j],     a0, bt[j][0], bt[j][2]);
                mma16(acc[0][2 * j + 1], a0, bt[j][1], bt[j][3]);
                mma16(acc[1][2 * j],     a1, bt[j][0], bt[j][2]);
                mma16(acc[1][2 * j + 1], a1, bt[j][1], bt[j][3]);
            }
        }
    }

    #pragma unroll
    for (int m = 0; m < 2; m++) {
        int r0 = bm + warpM * 32 + m * 16 + g;
        #pragma unroll
        for (int n = 0; n < 8; n++) {
            int c0 = warpN * 64 + n * 8 + 2 * t;
            *(__half2*)(C + (size_t)r0 * DD + c0) =
                __floats2half2_rn(acc[m][n][0], acc[m][n][1]);
            *(__half2*)(C + (size_t)(r0 + 8) * DD + c0) =
                __floats2half2_rn(acc[m][n][2], acc[m][n][3]);
        }
    }
}

// ========== fused Wo GEMM (fp16) + residual + bias + LayerNorm =============
#define WO_STAGE_B 49152
#define WO_SMEM    (3 * WO_STAGE_B)          // 147456 B

__global__ void __launch_bounds__(512, 1)
gemm_wo_ln(const __half* __restrict__ A, const __half* __restrict__ W,
           const float* __restrict__ h, const float* __restrict__ bo,
           const float* __restrict__ gg, const float* __restrict__ bb,
           float* __restrict__ outp) {
    extern __shared__ char smc[];
    const uint32_t sb = smem_u32(smc);
    float2* red = (float2*)smc;
    const int tid = threadIdx.x;
    const int lane = tid & 31;
    const int wid = tid >> 5;
    const int warpM = wid >> 2;
    const int warpN = wid & 3;
    const int bm = blockIdx.x * 128;
    const int g = lane >> 2;
    const int t = lane & 3;
    const int rr = lane & 7;
    const int half8 = (lane >> 3) & 1;
    const int hi = lane >> 4;
    const uint32_t rowA0 = (uint32_t)(warpM * 32 + half8 * 8 + rr);
    const uint32_t rowB0 = (uint32_t)(warpN * 64 + half8 * 8 + rr);

    float acc[2][8][4];
    #pragma unroll
    for (int m = 0; m < 2; m++)
        #pragma unroll
        for (int n = 0; n < 8; n++)
            #pragma unroll
            for (int j = 0; j < 4; j++) acc[m][n][j] = 0.f;

    const int lrow = tid >> 3;        // 0..63
    const int lcj  = tid & 7;

    auto load_stage = [&](int buf, int k0) {
        #pragma unroll
        for (int i = 0; i < 2; i++) {    // A: 128 rows
            int row = lrow + i * 64;
            uint32_t sw = (uint32_t)(lcj ^ (row & 7));
            cpa16(sb + (uint32_t)(buf * WO_STAGE_B + row * 128) + sw * 16,
                  A + (size_t)(bm + row) * DD + k0 + lcj * 8);
        }
        #pragma unroll
        for (int i = 0; i < 4; i++) {    // W: 256 rows
            int row = lrow + i * 64;
            uint32_t sw = (uint32_t)(lcj ^ (row & 7));
            cpa16(sb + (uint32_t)(buf * WO_STAGE_B + 16384 + row * 128) + sw * 16,
                  W + (size_t)row * DD + k0 + lcj * 8);
        }
    };

    load_stage(0, 0);  CP_COMMIT();
    load_stage(1, 64); CP_COMMIT();

    #pragma unroll 1
    for (int kk = 0; kk < 4; kk++) {
        if (kk < 3) CP_WAIT(1); else CP_WAIT(0);
        __syncthreads();
        if (kk < 2) { load_stage((kk + 2) % 3, (kk + 2) * 64); CP_COMMIT(); }

        const uint32_t aBase = sb + (uint32_t)((kk % 3) * WO_STAGE_B) + rowA0 * 128;
        const uint32_t bBase = sb + (uint32_t)((kk % 3) * WO_STAGE_B + 16384) + rowB0 * 128;
        #pragma unroll
        for (int ks = 0; ks < 4; ks++) {
            const uint32_t cob = (uint32_t)(((2 * ks + hi) ^ rr) << 4);
            uint32_t a0[4], a1[4];
            ldsm4(a0, aBase + cob);
            ldsm4(a1, aBase + 16 * 128 + cob);
            uint32_t bt[4][4];
            #pragma unroll
            for (int j = 0; j < 4; j++) ldsm4(bt[j], bBase + (uint32_t)(j * 16 * 128) + cob);
            #pragma unroll
            for (int j = 0; j < 4; j++) {
                mma16(acc[0][2 * j],     a0, bt[j][0], bt[j][2]);
                mma16(acc[0][2 * j + 1], a0, bt[j][1], bt[j][3]);
                mma16(acc[1][2 * j],     a1, bt[j][0], bt[j][2]);
                mma16(acc[1][2 * j + 1], a1, bt[j][1], bt[j][3]);
            }
        }
    }
    __syncthreads();   // mma reads done; smem reused for LN reduction

    // ---- epilogue: x = h + y + bo; per-row mean/var; normalize; store ----
    float2 bo2[8];
    #pragma unroll
    for (int n = 0; n < 8; n++)
        bo2[n] = *(const float2*)(bo + warpN * 64 + n * 8 + 2 * t);

    float s1[2][2], s2[2][2];
    #pragma unroll
    for (int m = 0; m < 2; m++) {
        int r0 = bm + warpM * 32 + m * 16 + g;
        s1[m][0] = s1[m][1] = s2[m][0] = s2[m][1] = 0.f;
        #pragma unroll
        for (int n = 0; n < 8; n++) {
            int coln = warpN * 64 + n * 8 + 2 * t;
            float2 ha = *(const float2*)(h + (size_t)r0 * DD + coln);
            float2 hb = *(const float2*)(h + (size_t)(r0 + 8) * DD + coln);
            float x0 = acc[m][n][0] + ha.x + bo2[n].x;
            float x1 = acc[m][n][1] + ha.y + bo2[n].y;
            float x2 = acc[m][n][2] + hb.x + bo2[n].x;
            float x3 = acc[m][n][3] + hb.y + bo2[n].y;
            acc[m][n][0] = x0; acc[m][n][1] = x1;
            acc[m][n][2] = x2; acc[m][n][3] = x3;
            s1[m][0] += x0 + x1;            s1[m][1] += x2 + x3;
            s2[m][0] += x0 * x0 + x1 * x1;  s2[m][1] += x2 * x2 + x3 * x3;
        }
    }
    #pragma unroll
    for (int m = 0; m < 2; m++)
        #pragma unroll
        for (int hh = 0; hh < 2; hh++) {
            s1[m][hh] += __shfl_xor_sync(0xffffffffu, s1[m][hh], 1);
            s1[m][hh] += __shfl_xor_sync(0xffffffffu, s1[m][hh], 2);
            s2[m][hh] += __shfl_xor_sync(0xffffffffu, s2[m][hh], 1);
            s2[m][hh] += __shfl_xor_sync(0xffffffffu, s2[m][hh], 2);
        }
    if (t == 0) {
        #pragma unroll
        for (int m = 0; m < 2; m++)
            #pragma unroll
            for (int hh = 0; hh < 2; hh++) {
                int row = warpM * 32 + m * 16 + g + hh * 8;
                red[row * 4 + warpN] = make_float2(s1[m][hh], s2[m][hh]);
            }
    }
    __syncthreads();

    #pragma unroll
    for (int m = 0; m < 2; m++) {
        #pragma unroll
        for (int hh = 0; hh < 2; hh++) {
            int row = warpM * 32 + m * 16 + g + hh * 8;
            float a1 = 0.f, a2 = 0.f;
            #pragma unroll
            for (int w2 = 0; w2 < 4; w2++) {
                float2 p = red[row * 4 + w2];
                a1 += p.x; a2 += p.y;
            }
            float mu = a1 * (1.0f / DD);
            float var = a2 * (1.0f / DD) - mu * mu;
            float rinv = rsqrtf(var + 1e-5f);
            size_t rbase = (size_t)(bm + row) * DD;
            #pragma unroll
            for (int n = 0; n < 8; n++) {
                int coln = warpN * 64 + n * 8 + 2 * t;
                float2 gv = *(const float2*)(gg + coln);
                float2 bv = *(const float2*)(bb + coln);
                float x0 = acc[m][n][hh * 2 + 0];
                float x1 = acc[m][n][hh * 2 + 1];
                float2 o;
                o.x = (x0 - mu) * rinv * gv.x + bv.x;
                o.y = (x1 - mu) * rinv * gv.y + bv.y;
                *(float2*)(outp + rbase + coln) = o;
            }
        }
    }
}

// ------- per-position attention (fp16 streams, deferred softmax) -----------
__global__ __launch_bounds__(256) void attn_kernel() {
    const int n = blockIdx.x;
    const int w = threadIdx.x >> 5;
    const int lane = threadIdx.x & 31;
    __shared__ float  sq[NH][SS][36];        // fp32 q (converted once)
    __shared__ float  satt[NH][SS][20];      // unnormalized exp(score)
    __shared__ __half st16[NH][2][SS][32];   // fp16 staging: [0]=q, [1]=k

    const size_t rowbase = (size_t)n * DD + w * 32;

    // ---- async stage q,k fp16: 17 rows x 4 chunks x 2 arrays = 136 chunks --
    {
        const __half* srcs[2] = {g_q16 + rowbase, g_k16 + rowbase};
        const uint32_t d0 = smem_u32(&st16[w][0][0][0]);
        #pragma unroll
        for (int pass = 0; pass < 5; pass++) {
            int idx = pass * 32 + lane;
            if (idx < 136) {
                int s = idx >> 3;
                int which = (idx >> 2) & 1;
                int c = idx & 3;
                cpa16(d0 + (uint32_t)((which * SS + s) * 64 + c * 16),
                      srcs[which] + (size_t)s * NPOS * DD + c * 8);
            }
        }
        CP_COMMIT();
    }

    // ---- mask + v loads overlap the cp.async group ----
    unsigned char mr = 0;
    if (lane >= 1 && lane < SS) mr = g_mask[lane * NPOS + n];

    float vv[SS];
    const size_t coloff = rowbase + lane;
    #pragma unroll
    for (int s = 0; s < SS; s++)
        vv[s] = __half2float(g_v16[coloff + (size_t)s * NPOS * DD]);

    unsigned bits = __ballot_sync(0xffffffffu, mr != 0);
    if (bits & 0x1FFFEu) bits |= 1u;

    CP_WAIT(0);
    __syncwarp();

    // convert q -> fp32 smem (272 half2 per warp)
    #pragma unroll
    for (int j = 0; j < 9; j++) {
        int idx = j * 32 + lane;
        if (idx < 272) {
            int s = idx >> 4;
            int c2 = idx & 15;
            float2 f = __half22float2(*(__half2*)&st16[w][0][s][2 * c2]);
            *(float2*)&sq[w][s][2 * c2] = f;
        }
    }
    __syncwarp();

    const float scale = 0.17677669529663687f;  // 1/sqrt(32)
    const bool key_act = (lane < SS) && ((bits >> lane) & 1u);

    // k row -> registers (fp16 -> fp32), loop-invariant across s
    float kk[32];
    if (key_act) {
        #pragma unroll
        for (int j = 0; j < 16; j++) {
            float2 f = __half22float2(*(__half2*)&st16[w][1][lane][2 * j]);
            kk[2 * j] = f.x;
            kk[2 * j + 1] = f.y;
        }
    }

    // score phase: store UNNORMALIZED p
    #pragma unroll 1
    for (int s = 0; s < SS; s++) {
        if (!((bits >> s) & 1u)) continue;      // warp-uniform
        float p = 0.f;
        if (key_act) {
            float a0 = 0.f, a1 = 0.f;
            #pragma unroll
            for (int c = 0; c < 32; c += 8) {
                float4 q0 = *(const float4*)&sq[w][s][c];       // broadcast
                float4 q1 = *(const float4*)&sq[w][s][c + 4];   // broadcast
                a0 += q0.x * kk[c + 0] + q0.y * kk[c + 1] +
                      q0.z * kk[c + 2] + q0.w * kk[c + 3];
                a1 += q1.x * kk[c + 4] + q1.y * kk[c + 5] +
                      q1.z * kk[c + 6] + q1.w * kk[c + 7];
            }
            p = __expf((a0 + a1) * scale);      // shift-invariant: no max needed
        }
        if (lane < SS) satt[w][s][lane] = p;
    }
    __syncwarp();

    // out phase: res = (Σ p·v) / (Σ p)
    #pragma unroll 1
    for (int s = 0; s < SS; s++) {
        float res;
        if ((bits >> s) & 1u) {
            const float4* arow = (const float4*)&satt[w][s][0];
            float acc = 0.f, ps = 0.f;
            #pragma unroll
            for (int j = 0; j < 4; j++) {
                float4 a4 = arow[j];
                acc += a4.x * vv[4 * j + 0] + a4.y * vv[4 * j + 1] +
                       a4.z * vv[4 * j + 2] + a4.w * vv[4 * j + 3];
                ps  += (a4.x + a4.y) + (a4.z + a4.w);
            }
            float a16 = satt[w][s][16];
            acc += a16 * vv[16];
            ps  += a16;
            res = acc * __frcp_rn(ps);
        } else {
            res = vv[s];
        }
        g_o16[coloff + (size_t)s * NPOS * DD] = __float2half_rn(res);
    }
}

// ---------------- launch ----------------
extern "C" void kernel_launch(void* const* d_in, const int* in_sizes, int n_in,
                              void* d_out, int out_size) {
    (void)in_sizes; (void)n_in; (void)out_size;
    const float* h  = (const float*)d_in[0];
    const void*  mm = d_in[2];
    const float* Wq = (const float*)d_in[3];
    const float* Wk = (const float*)d_in[4];
    const float* Wv = (const float*)d_in[5];
    const float* Wo = (const float*)d_in[6];
    const float* bo = (const float*)d_in[7];
    const float* lg = (const float*)d_in[8];
    const float* lb = (const float*)d_in[9];
    float* out = (float*)d_out;

    __half *ph, *pq, *pk, *pv, *po, *pw;
    cudaGetSymbolAddress((void**)&ph, g_h16);
    cudaGetSymbolAddress((void**)&pq, g_q16);
    cudaGetSymbolAddress((void**)&pk, g_k16);
    cudaGetSymbolAddress((void**)&pv, g_v16);
    cudaGetSymbolAddress((void**)&po, g_o16);
    cudaGetSymbolAddress((void**)&pw, g_w16);

    cudaFuncSetAttribute(gemm_qkv, cudaFuncAttributeMaxDynamicSharedMemorySize, QKV_SMEM);
    cudaFuncSetAttribute(gemm_wo_ln, cudaFuncAttributeMaxDynamicSharedMemorySize, WO_SMEM);

    mask_prep<<<64, 256>>>((const unsigned char*)mm);
    conv_h16<<<MTOT * DD / 2048, 256>>>((const float4*)h);
    conv_w16<<<128, 256>>>((const float4*)Wq, (const float4*)Wk,
                           (const float4*)Wv, (const float4*)Wo);

    gemm_qkv<<<dim3(3, MTOT / 128), 512, QKV_SMEM>>>(
        ph, pw + 0 * DD * DD, pw + 1 * DD * DD, pw + 2 * DD * DD, pq, pk, pv);

    attn_kernel<<<NPOS, 256>>>();

    gemm_wo_ln<<<MTOT / 128, 512, WO_SMEM>>>(po, pw + 3 * DD * DD,
                                             h, bo, lg, lb, out);
}

// round 17
// speedup vs baseline: 1.5961x; 1.1119x over previous
#include <cuda_runtime.h>
#include <cuda_fp16.h>
#include <math.h>
#include <stdint.h>

#define SS   17
#define NPOS 4096
#define DD   256
#define NH   8
#define MTOT (SS * NPOS)   // 69632

// ---------------- scratch (allocation-free: device globals) ----------------
// s-major layout (row = s*NPOS + n), all fp16
__device__ __half g_h16[(size_t)MTOT * DD];
__device__ __half g_q16[(size_t)MTOT * DD];
__device__ __half g_k16[(size_t)MTOT * DD];
__device__ __half g_v16[(size_t)MTOT * DD];
__device__ __half g_o16[(size_t)MTOT * DD];
__device__ __half g_w16[4][DD * DD];          // fp16(Wq,Wk,Wv,Wo)
__device__ unsigned char g_mask[SS * NPOS];   // rows 1..16 = msta (row 0 unused)

// ---------------- helpers ----------------
__device__ __forceinline__ uint32_t smem_u32(const void* p) {
    uint32_t a;
    asm("{ .reg .u64 t; cvta.to.shared.u64 t, %1; cvt.u32.u64 %0, t; }" : "=r"(a) : "l"(p));
    return a;
}
__device__ __forceinline__ void cpa16(uint32_t dst, const void* src) {
    asm volatile("cp.async.cg.shared.global [%0], [%1], 16;" :: "r"(dst), "l"(src));
}
#define CP_COMMIT() asm volatile("cp.async.commit_group;" ::: "memory")
#define CP_WAIT(n)  asm volatile("cp.async.wait_group %0;" :: "n"(n) : "memory")

__device__ __forceinline__ void ldsm4(uint32_t* r, uint32_t addr) {
    asm volatile("ldmatrix.sync.aligned.m8n8.x4.shared.b16 {%0,%1,%2,%3}, [%4];"
                 : "=r"(r[0]), "=r"(r[1]), "=r"(r[2]), "=r"(r[3]) : "r"(addr));
}
// fp16 mma: D(4xf32) += A(4xb32) * B(2xb32)
__device__ __forceinline__ void mma16(float* c, const uint32_t* a, uint32_t b0, uint32_t b1) {
    asm volatile(
        "mma.sync.aligned.m16n8k16.row.col.f32.f16.f16.f32 "
        "{%0,%1,%2,%3}, {%4,%5,%6,%7}, {%8,%9}, {%0,%1,%2,%3};"
        : "+f"(c[0]), "+f"(c[1]), "+f"(c[2]), "+f"(c[3])
        : "r"(a[0]), "r"(a[1]), "r"(a[2]), "r"(a[3]), "r"(b0), "r"(b1));
}

// ---------------- mask canonicalization (dtype-robust, parallel) ----------------
__global__ void mask_prep(const unsigned char* __restrict__ mraw) {
    __shared__ int s_nz1;
    int tid = threadIdx.x;
    if (tid == 0) s_nz1 = 0;
    __syncthreads();
    int l1 = 0;
    for (int i = tid; i < 4096; i += blockDim.x)
        if ((i & 3) == 1 && mraw[i] != 0) l1 = 1;
    if (l1) atomicOr(&s_nz1, 1);
    __syncthreads();
    bool u8fmt = (s_nz1 != 0);
    const unsigned int* mw = (const unsigned int*)mraw;
    int i = blockIdx.x * 1024 + tid;
    for (int r = 0; r < 4; r++, i += 256) {
        unsigned char m = u8fmt ? (mraw[i] != 0) : (mw[i] != 0u);
        g_mask[NPOS + i] = m;
    }
}

// ---------------- fp16 pre-conversion (rna) ----------------
__global__ void conv_h16(const float4* __restrict__ src) {
    size_t i = (size_t)blockIdx.x * 256 + threadIdx.x;   // 8 floats per thread
    float4 a = src[2 * i];
    float4 b = src[2 * i + 1];
    __half2 h[4];
    h[0] = __floats2half2_rn(a.x, a.y);
    h[1] = __floats2half2_rn(a.z, a.w);
    h[2] = __floats2half2_rn(b.x, b.y);
    h[3] = __floats2half2_rn(b.z, b.w);
    *(uint4*)(g_h16 + i * 8) = *(uint4*)h;
}
__global__ void conv_w16(const float4* __restrict__ w0, const float4* __restrict__ w1,
                         const float4* __restrict__ w2, const float4* __restrict__ w3) {
    const float4* srcs[4] = {w0, w1, w2, w3};
    int mat = blockIdx.x >> 5;
    int i = (blockIdx.x & 31) * 256 + threadIdx.x;
    float4 a = srcs[mat][2 * i];
    float4 b = srcs[mat][2 * i + 1];
    __half2 h[4];
    h[0] = __floats2half2_rn(a.x, a.y);
    h[1] = __floats2half2_rn(a.z, a.w);
    h[2] = __floats2half2_rn(b.x, b.y);
    h[3] = __floats2half2_rn(b.z, b.w);
    *(uint4*)(&g_w16[mat][0] + (size_t)i * 8) = *(uint4*)h;
}

// ============ fused QKV GEMM (fp16): grid (6, 544), BK=64, 3-stage =========
// (R14 configuration — best measured: 92.5us)
#define QKV_STAGE_B 32768
#define QKV_SMEM    (3 * QKV_STAGE_B)        // 98304 B

__global__ void __launch_bounds__(256, 2)
gemm_qkv(const __half* __restrict__ A,
         const __half* __restrict__ W0, const __half* __restrict__ W1,
         const __half* __restrict__ W2,
         __half* __restrict__ C0, __half* __restrict__ C1, __half* __restrict__ C2) {
    extern __shared__ char smc[];
    const uint32_t sb = smem_u32(smc);
    const int out = blockIdx.x >> 1;
    const int bn = (blockIdx.x & 1) * 128;
    const int bm = blockIdx.y * 128;
    const __half* W = (out == 0) ? W0 : (out == 1) ? W1 : W2;
    __half* C = (out == 0) ? C0 : (out == 1) ? C1 : C2;

    const int tid = threadIdx.x;
    const int lane = tid & 31;
    const int wid = tid >> 5;
    const int warpM = wid >> 1;
    const int warpN = wid & 1;
    const int g = lane >> 2;
    const int t = lane & 3;
    const int rr = lane & 7;
    const int half8 = (lane >> 3) & 1;
    const int hi = lane >> 4;
    const uint32_t rowA0 = (uint32_t)(warpM * 32 + half8 * 8 + rr);
    const uint32_t rowB0 = (uint32_t)(warpN * 64 + half8 * 8 + rr);

    float acc[2][8][4];
    #pragma unroll
    for (int m = 0; m < 2; m++)
        #pragma unroll
        for (int n = 0; n < 8; n++)
            #pragma unroll
            for (int j = 0; j < 4; j++) acc[m][n][j] = 0.f;

    const int lrow = tid >> 3;        // 0..31
    const int lcj  = tid & 7;         // chunk 0..7

    auto load_stage = [&](int buf, int k0) {
        #pragma unroll
        for (int i = 0; i < 4; i++) {
            int row = lrow + i * 32;
            uint32_t sw = (uint32_t)(lcj ^ (row & 7));
            uint32_t dst = sb + (uint32_t)(buf * QKV_STAGE_B + row * 128) + sw * 16;
            cpa16(dst, A + (size_t)(bm + row) * DD + k0 + lcj * 8);
            cpa16(dst + 16384, W + (size_t)(bn + row) * DD + k0 + lcj * 8);
        }
    };

    load_stage(0, 0);  CP_COMMIT();
    load_stage(1, 64); CP_COMMIT();

    #pragma unroll 1
    for (int kk = 0; kk < 4; kk++) {
        if (kk < 3) CP_WAIT(1); else CP_WAIT(0);
        __syncthreads();
        if (kk < 2) { load_stage((kk + 2) % 3, (kk + 2) * 64); CP_COMMIT(); }

        const uint32_t aBase = sb + (uint32_t)((kk % 3) * QKV_STAGE_B) + rowA0 * 128;
        const uint32_t bBase = sb + (uint32_t)((kk % 3) * QKV_STAGE_B + 16384) + rowB0 * 128;
        #pragma unroll
        for (int ks = 0; ks < 4; ks++) {
            const uint32_t cob = (uint32_t)(((2 * ks + hi) ^ rr) << 4);
            uint32_t a0[4], a1[4];
            ldsm4(a0, aBase + cob);
            ldsm4(a1, aBase + 16 * 128 + cob);
            uint32_t bt[4][4];
            #pragma unroll
            for (int j = 0; j < 4; j++) ldsm4(bt[j], bBase + (uint32_t)(j * 16 * 128) + cob);
            #pragma unroll
            for (int j = 0; j < 4; j++) {
                mma16(acc[0][2 * j],     a0, bt[j][0], bt[j][2]);
                mma16(acc[0][2 * j + 1], a0, bt[j][1], bt[j][3]);
                mma16(acc[1][2 * j],     a1, bt[j][0], bt[j][2]);
                mma16(acc[1][2 * j + 1], a1, bt[j][1], bt[j][3]);
            }
        }
    }

    #pragma unroll
    for (int m = 0; m < 2; m++) {
        int r0 = bm + warpM * 32 + m * 16 + g;
        #pragma unroll
        for (int n = 0; n < 8; n++) {
            int c0 = bn + warpN * 64 + n * 8 + 2 * t;
            *(__half2*)(C + (size_t)r0 * DD + c0) =
                __floats2half2_rn(acc[m][n][0], acc[m][n][1]);
            *(__half2*)(C + (size_t)(r0 + 8) * DD + c0) =
                __floats2half2_rn(acc[m][n][2], acc[m][n][3]);
        }
    }
}

// ========== fused Wo GEMM (fp16) + residual + bias + LayerNorm =============
// BM=64, BN=256, 256 threads (8 warps 2Mx4N), 2-stage double buffer.
// stage = A 64x64h (8KB) + W 256x64h (32KB) = 40KB; 2 stages = 80KB -> 2 CTAs/SM.
#define WO_STAGE_B 40960
#define WO_SMEM    (2 * WO_STAGE_B)          // 81920 B

__global__ void __launch_bounds__(256, 2)
gemm_wo_ln(const __half* __restrict__ A, const __half* __restrict__ W,
           const float* __restrict__ h, const float* __restrict__ bo,
           const float* __restrict__ gg, const float* __restrict__ bb,
           float* __restrict__ outp) {
    extern __shared__ char smc[];
    const uint32_t sb = smem_u32(smc);
    float2* red = (float2*)smc;
    const int tid = threadIdx.x;
    const int lane = tid & 31;
    const int wid = tid >> 5;
    const int warpM = wid >> 2;       // 0..1
    const int warpN = wid & 3;        // 0..3
    const int bm = blockIdx.x * 64;
    const int g = lane >> 2;
    const int t = lane & 3;
    const int rr = lane & 7;
    const int half8 = (lane >> 3) & 1;
    const int hi = lane >> 4;
    const uint32_t rowA0 = (uint32_t)(warpM * 32 + half8 * 8 + rr);   // 0..63
    const uint32_t rowB0 = (uint32_t)(warpN * 64 + half8 * 8 + rr);   // 0..255

    float acc[2][8][4];
    #pragma unroll
    for (int m = 0; m < 2; m++)
        #pragma unroll
        for (int n = 0; n < 8; n++)
            #pragma unroll
            for (int j = 0; j < 4; j++) acc[m][n][j] = 0.f;

    const int lrow = tid >> 3;        // 0..31
    const int lcj  = tid & 7;

    auto load_stage = [&](int buf, int k0) {
        #pragma unroll
        for (int i = 0; i < 2; i++) {    // A: 64 rows
            int row = lrow + i * 32;
            uint32_t sw = (uint32_t)(lcj ^ (row & 7));
            cpa16(sb + (uint32_t)(buf * WO_STAGE_B + row * 128) + sw * 16,
                  A + (size_t)(bm + row) * DD + k0 + lcj * 8);
        }
        #pragma unroll
        for (int i = 0; i < 8; i++) {    // W: 256 rows
            int row = lrow + i * 32;
            uint32_t sw = (uint32_t)(lcj ^ (row & 7));
            cpa16(sb + (uint32_t)(buf * WO_STAGE_B + 8192 + row * 128) + sw * 16,
                  W + (size_t)row * DD + k0 + lcj * 8);
        }
    };

    load_stage(0, 0); CP_COMMIT();

    #pragma unroll 1
    for (int kk = 0; kk < 4; kk++) {
        if (kk < 3) {
            load_stage((kk + 1) & 1, (kk + 1) * 64);
            CP_COMMIT();
            CP_WAIT(1);
        } else {
            CP_WAIT(0);
        }
        __syncthreads();

        const uint32_t aBase = sb + (uint32_t)((kk & 1) * WO_STAGE_B) + rowA0 * 128;
        const uint32_t bBase = sb + (uint32_t)((kk & 1) * WO_STAGE_B + 8192) + rowB0 * 128;
        #pragma unroll
        for (int ks = 0; ks < 4; ks++) {
            const uint32_t cob = (uint32_t)(((2 * ks + hi) ^ rr) << 4);
            uint32_t a0[4], a1[4];
            ldsm4(a0, aBase + cob);
            ldsm4(a1, aBase + 16 * 128 + cob);
            uint32_t bt[4][4];
            #pragma unroll
            for (int j = 0; j < 4; j++) ldsm4(bt[j], bBase + (uint32_t)(j * 16 * 128) + cob);
            #pragma unroll
            for (int j = 0; j < 4; j++) {
                mma16(acc[0][2 * j],     a0, bt[j][0], bt[j][2]);
                mma16(acc[0][2 * j + 1], a0, bt[j][1], bt[j][3]);
                mma16(acc[1][2 * j],     a1, bt[j][0], bt[j][2]);
                mma16(acc[1][2 * j + 1], a1, bt[j][1], bt[j][3]);
            }
        }
        __syncthreads();   // reads done before next iter overwrites this buffer
    }

    // ---- epilogue: x = h + y + bo; per-row mean/var; normalize; store ----
    float2 bo2[8];
    #pragma unroll
    for (int n = 0; n < 8; n++)
        bo2[n] = *(const float2*)(bo + warpN * 64 + n * 8 + 2 * t);

    float s1[2][2], s2[2][2];
    #pragma unroll
    for (int m = 0; m < 2; m++) {
        int r0 = bm + warpM * 32 + m * 16 + g;
        s1[m][0] = s1[m][1] = s2[m][0] = s2[m][1] = 0.f;
        #pragma unroll
        for (int n = 0; n < 8; n++) {
            int coln = warpN * 64 + n * 8 + 2 * t;
            float2 ha = *(const float2*)(h + (size_t)r0 * DD + coln);
            float2 hb = *(const float2*)(h + (size_t)(r0 + 8) * DD + coln);
            float x0 = acc[m][n][0] + ha.x + bo2[n].x;
            float x1 = acc[m][n][1] + ha.y + bo2[n].y;
            float x2 = acc[m][n][2] + hb.x + bo2[n].x;
            float x3 = acc[m][n][3] + hb.y + bo2[n].y;
            acc[m][n][0] = x0; acc[m][n][1] = x1;
            acc[m][n][2] = x2; acc[m][n][3] = x3;
            s1[m][0] += x0 + x1;            s1[m][1] += x2 + x3;
            s2[m][0] += x0 * x0 + x1 * x1;  s2[m][1] += x2 * x2 + x3 * x3;
        }
    }
    #pragma unroll
    for (int m = 0; m < 2; m++)
        #pragma unroll
        for (int hh = 0; hh < 2; hh++) {
            s1[m][hh] += __shfl_xor_sync(0xffffffffu, s1[m][hh], 1);
            s1[m][hh] += __shfl_xor_sync(0xffffffffu, s1[m][hh], 2);
            s2[m][hh] += __shfl_xor_sync(0xffffffffu, s2[m][hh], 1);
            s2[m][hh] += __shfl_xor_sync(0xffffffffu, s2[m][hh], 2);
        }
    if (t == 0) {
        #pragma unroll
        for (int m = 0; m < 2; m++)
            #pragma unroll
            for (int hh = 0; hh < 2; hh++) {
                int row = warpM * 32 + m * 16 + g + hh * 8;   // 0..63
                red[row * 4 + warpN] = make_float2(s1[m][hh], s2[m][hh]);
            }
    }
    __syncthreads();

    #pragma unroll
    for (int m = 0; m < 2; m++) {
        #pragma unroll
        for (int hh = 0; hh < 2; hh++) {
            int row = warpM * 32 + m * 16 + g + hh * 8;
            float a1 = 0.f, a2 = 0.f;
            #pragma unroll
            for (int w2 = 0; w2 < 4; w2++) {
                float2 p = red[row * 4 + w2];
                a1 += p.x; a2 += p.y;
            }
            float mu = a1 * (1.0f / DD);
            float var = a2 * (1.0f / DD) - mu * mu;
            float rinv = rsqrtf(var + 1e-5f);
            size_t rbase = (size_t)(bm + row) * DD;
            #pragma unroll
            for (int n = 0; n < 8; n++) {
                int coln = warpN * 64 + n * 8 + 2 * t;
                float2 gv = *(const float2*)(gg + coln);
                float2 bv = *(const float2*)(bb + coln);
                float x0 = acc[m][n][hh * 2 + 0];
                float x1 = acc[m][n][hh * 2 + 1];
                float2 o;
                o.x = (x0 - mu) * rinv * gv.x + bv.x;
                o.y = (x1 - mu) * rinv * gv.y + bv.y;
                *(float2*)(outp + rbase + coln) = o;
            }
        }
    }
}

// ------- per-position attention (fp16 streams, deferred softmax) -----------
__global__ __launch_bounds__(256) void attn_kernel() {
    const int n = blockIdx.x;
    const int w = threadIdx.x >> 5;
    const int lane = threadIdx.x & 31;
    __shared__ float  sq[NH][SS][36];        // fp32 q (converted once)
    __shared__ float  satt[NH][SS][20];      // unnormalized exp(score)
    __shared__ __half st16[NH][2][SS][32];   // fp16 staging: [0]=q, [1]=k

    const size_t rowbase = (size_t)n * DD + w * 32;

    // ---- async stage q,k fp16: 17 rows x 4 chunks x 2 arrays = 136 chunks --
    {
        const __half* srcs[2] = {g_q16 + rowbase, g_k16 + rowbase};
        const uint32_t d0 = smem_u32(&st16[w][0][0][0]);
        #pragma unroll
        for (int pass = 0; pass < 5; pass++) {
            int idx = pass * 32 + lane;
            if (idx < 136) {
                int s = idx >> 3;
                int which = (idx >> 2) & 1;
                int c = idx & 3;
                cpa16(d0 + (uint32_t)((which * SS + s) * 64 + c * 16),
                      srcs[which] + (size_t)s * NPOS * DD + c * 8);
            }
        }
        CP_COMMIT();
    }

    // ---- mask + v loads overlap the cp.async group ----
    unsigned char mr = 0;
    if (lane >= 1 && lane < SS) mr = g_mask[lane * NPOS + n];

    float vv[SS];
    const size_t coloff = rowbase + lane;
    #pragma unroll
    for (int s = 0; s < SS; s++)
        vv[s] = __half2float(g_v16[coloff + (size_t)s * NPOS * DD]);

    unsigned bits = __ballot_sync(0xffffffffu, mr != 0);
    if (bits & 0x1FFFEu) bits |= 1u;

    CP_WAIT(0);
    __syncwarp();

    // convert q -> fp32 smem (272 half2 per warp)
    #pragma unroll
    for (int j = 0; j < 9; j++) {
        int idx = j * 32 + lane;
        if (idx < 272) {
            int s = idx >> 4;
            int c2 = idx & 15;
            float2 f = __half22float2(*(__half2*)&st16[w][0][s][2 * c2]);
            *(float2*)&sq[w][s][2 * c2] = f;
        }
    }
    __syncwarp();

    const float scale = 0.17677669529663687f;  // 1/sqrt(32)
    const bool key_act = (lane < SS) && ((bits >> lane) & 1u);

    // k row -> registers (fp16 -> fp32), loop-invariant across s
    float kk[32];
    if (key_act) {
        #pragma unroll
        for (int j = 0; j < 16; j++) {
            float2 f = __half22float2(*(__half2*)&st16[w][1][lane][2 * j]);
            kk[2 * j] = f.x;
            kk[2 * j + 1] = f.y;
        }
    }

    // score phase: store UNNORMALIZED p
    #pragma unroll 1
    for (int s = 0; s < SS; s++) {
        if (!((bits >> s) & 1u)) continue;      // warp-uniform
        float p = 0.f;
        if (key_act) {
            float a0 = 0.f, a1 = 0.f;
            #pragma unroll
            for (int c = 0; c < 32; c += 8) {
                float4 q0 = *(const float4*)&sq[w][s][c];       // broadcast
                float4 q1 = *(const float4*)&sq[w][s][c + 4];   // broadcast
                a0 += q0.x * kk[c + 0] + q0.y * kk[c + 1] +
                      q0.z * kk[c + 2] + q0.w * kk[c + 3];
                a1 += q1.x * kk[c + 4] + q1.y * kk[c + 5] +
                      q1.z * kk[c + 6] + q1.w * kk[c + 7];
            }
            p = __expf((a0 + a1) * scale);      // shift-invariant: no max needed
        }
        if (lane < SS) satt[w][s][lane] = p;
    }
    __syncwarp();

    // out phase: res = (Σ p·v) / (Σ p)
    #pragma unroll 1
    for (int s = 0; s < SS; s++) {
        float res;
        if ((bits >> s) & 1u) {
            const float4* arow = (const float4*)&satt[w][s][0];
            float acc = 0.f, ps = 0.f;
            #pragma unroll
            for (int j = 0; j < 4; j++) {
                float4 a4 = arow[j];
                acc += a4.x * vv[4 * j + 0] + a4.y * vv[4 * j + 1] +
                       a4.z * vv[4 * j + 2] + a4.w * vv[4 * j + 3];
                ps  += (a4.x + a4.y) + (a4.z + a4.w);
            }
            float a16 = satt[w][s][16];
            acc += a16 * vv[16];
            ps  += a16;
            res = acc * __frcp_rn(ps);
        } else {
            res = vv[s];
        }
        g_o16[coloff + (size_t)s * NPOS * DD] = __float2half_rn(res);
    }
}

// ---------------- launch ----------------
extern "C" void kernel_launch(void* const* d_in, const int* in_sizes, int n_in,
                              void* d_out, int out_size) {
    (void)in_sizes; (void)n_in; (void)out_size;
    const float* h  = (const float*)d_in[0];
    const void*  mm = d_in[2];
    const float* Wq = (const float*)d_in[3];
    const float* Wk = (const float*)d_in[4];
    const float* Wv = (const float*)d_in[5];
    const float* Wo = (const float*)d_in[6];
    const float* bo = (const float*)d_in[7];
    const float* lg = (const float*)d_in[8];
    const float* lb = (const float*)d_in[9];
    float* out = (float*)d_out;

    __half *ph, *pq, *pk, *pv, *po, *pw;
    cudaGetSymbolAddress((void**)&ph, g_h16);
    cudaGetSymbolAddress((void**)&pq, g_q16);
    cudaGetSymbolAddress((void**)&pk, g_k16);
    cudaGetSymbolAddress((void**)&pv, g_v16);
    cudaGetSymbolAddress((void**)&po, g_o16);
    cudaGetSymbolAddress((void**)&pw, g_w16);

    cudaFuncSetAttribute(gemm_qkv, cudaFuncAttributeMaxDynamicSharedMemorySize, QKV_SMEM);
    cudaFuncSetAttribute(gemm_wo_ln, cudaFuncAttributeMaxDynamicSharedMemorySize, WO_SMEM);

    mask_prep<<<64, 256>>>((const unsigned char*)mm);
    conv_h16<<<MTOT * DD / 2048, 256>>>((const float4*)h);
    conv_w16<<<128, 256>>>((const float4*)Wq, (const float4*)Wk,
                           (const float4*)Wv, (const float4*)Wo);

    gemm_qkv<<<dim3(6, MTOT / 128), 256, QKV_SMEM>>>(
        ph, pw + 0 * DD * DD, pw + 1 * DD * DD, pw + 2 * DD * DD, pq, pk, pv);

    attn_kernel<<<NPOS, 256>>>();

    gemm_wo_ln<<<MTOT / 64, 256, WO_SMEM>>>(po, pw + 3 * DD * DD,
                                            h, bo, lg, lb, out);
}